// round 7
// baseline (speedup 1.0000x reference)
#include <cuda_runtime.h>

#define B_  1024
#define I_  256
#define N_  512
#define D_  6
#define U_  16
#define L_  64
#define ND_ (N_ * D_)   // 3072

__device__ float g_W  [I_ * ND_];   // sparsemax(feature_selection_logits), [I][ND]
__device__ float g_FVt[ND_ * B_];   // feature values TRANSPOSED, [ND][B]
__device__ float g_sc [ND_];        // 0.5*exp(-lt)
__device__ float g_of [ND_];        // 0.5 - th*0.5*exp(-lt)

typedef unsigned long long u64;

__device__ __forceinline__ void fma2(u64 &acc, u64 a, u64 b) {
    asm("fma.rn.f32x2 %0, %1, %2, %0;" : "+l"(acc) : "l"(a), "l"(b));
}
__device__ __forceinline__ u64 pack2(float lo, float hi) {
    u64 r; asm("mov.b64 %0, {%1, %2};" : "=l"(r) : "f"(lo), "f"(hi)); return r;
}
__device__ __forceinline__ void unpack2(float &lo, float &hi, u64 v) {
    asm("mov.b64 {%0, %1}, %2;" : "=f"(lo), "=f"(hi) : "l"(v));
}
__device__ __forceinline__ u64 d2l(double d) { return __double_as_longlong(d); }

// ---------------------------------------------------------------------------
// Kernel A: sparsemax over last axis (D=6) for each (i, n)
// ---------------------------------------------------------------------------
__global__ void k_sparsemax(const float* __restrict__ fsl) {
    int idx = blockIdx.x * blockDim.x + threadIdx.x;
    if (idx >= I_ * N_) return;
    const float* z = fsl + (size_t)idx * D_;
    float z0 = z[0], z1 = z[1], z2 = z[2], z3 = z[3], z4 = z[4], z5 = z[5];
    float s0 = z0, s1 = z1, s2 = z2, s3 = z3, s4 = z4, s5 = z5;

#define CSWP(a, b) { float _mx = fmaxf(a, b); float _mn = fminf(a, b); a = _mx; b = _mn; }
    CSWP(s1, s2) CSWP(s4, s5) CSWP(s0, s2) CSWP(s3, s5)
    CSWP(s0, s1) CSWP(s3, s4) CSWP(s2, s5) CSWP(s0, s3)
    CSWP(s1, s4) CSWP(s2, s4) CSWP(s1, s3) CSWP(s2, s3)
#undef CSWP

    float cs = s0; int k = 1; float ts = cs;
    cs += s1; if (1.0f + 2.0f * s1 > cs) { k = 2; ts = cs; }
    cs += s2; if (1.0f + 3.0f * s2 > cs) { k = 3; ts = cs; }
    cs += s3; if (1.0f + 4.0f * s3 > cs) { k = 4; ts = cs; }
    cs += s4; if (1.0f + 5.0f * s4 > cs) { k = 5; ts = cs; }
    cs += s5; if (1.0f + 6.0f * s5 > cs) { k = 6; ts = cs; }
    float tau = (ts - 1.0f) / (float)k;

    float* w = g_W + (size_t)idx * D_;
    w[0] = fmaxf(z0 - tau, 0.0f);
    w[1] = fmaxf(z1 - tau, 0.0f);
    w[2] = fmaxf(z2 - tau, 0.0f);
    w[3] = fmaxf(z3 - tau, 0.0f);
    w[4] = fmaxf(z4 - tau, 0.0f);
    w[5] = fmaxf(z5 - tau, 0.0f);
}

__global__ void k_scaleoff(const float* __restrict__ th, const float* __restrict__ lt) {
    int idx = blockIdx.x * blockDim.x + threadIdx.x;
    if (idx >= ND_) return;
    float s = 0.5f * expf(-lt[idx]);
    g_sc[idx] = s;
    g_of[idx] = 0.5f - th[idx] * s;
}

// ---------------------------------------------------------------------------
// Kernel B: FVt[m=nd][j=b] = sum_k W[k][m] * x[j][k]  (unchanged)
// ---------------------------------------------------------------------------
__global__ void __launch_bounds__(256, 2) k_gemm(const float* __restrict__ x) {
    __shared__ float As[16][128];   // [k][m]
    __shared__ float Bs[16][68];    // [k][j], padded

    int t  = threadIdx.x;
    int tx = t & 15;
    int ty = t >> 4;
    int j0 = blockIdx.x * 64;
    int m0 = blockIdx.y * 128;

    int ak = t >> 4, amc = (t & 15) * 8;
    int bj = t >> 2, bkq = (t & 3) * 4;
    const float* aBase = g_W + (size_t)ak * ND_ + m0 + amc;
    const float* bBase = x + (size_t)(j0 + bj) * I_ + bkq;

    u64 acc2[4][4];
#pragma unroll
    for (int i = 0; i < 4; i++)
#pragma unroll
        for (int j = 0; j < 4; j++) acc2[i][j] = 0ull;

    float4 pa0 = *(const float4*)(aBase);
    float4 pa1 = *(const float4*)(aBase + 4);
    float4 pb  = *(const float4*)(bBase);

    for (int kt = 0; kt < I_; kt += 16) {
        *(float4*)&As[ak][amc]     = pa0;
        *(float4*)&As[ak][amc + 4] = pa1;
        Bs[bkq + 0][bj] = pb.x; Bs[bkq + 1][bj] = pb.y;
        Bs[bkq + 2][bj] = pb.z; Bs[bkq + 3][bj] = pb.w;
        __syncthreads();

        if (kt + 16 < I_) {
            pa0 = *(const float4*)(aBase + (size_t)(kt + 16) * ND_);
            pa1 = *(const float4*)(aBase + (size_t)(kt + 16) * ND_ + 4);
            pb  = *(const float4*)(bBase + kt + 16);
        }

#pragma unroll
        for (int kk = 0; kk < 16; kk++) {
            double2 a01 = *(const double2*)&As[kk][ty * 8];
            double2 a23 = *(const double2*)&As[kk][ty * 8 + 4];
            float4  bv  = *(const float4*)&Bs[kk][tx * 4];
            u64 am[4] = { d2l(a01.x), d2l(a01.y), d2l(a23.x), d2l(a23.y) };
            u64 bd[4] = { pack2(bv.x, bv.x), pack2(bv.y, bv.y),
                          pack2(bv.z, bv.z), pack2(bv.w, bv.w) };
#pragma unroll
            for (int mp = 0; mp < 4; mp++)
#pragma unroll
                for (int j = 0; j < 4; j++) fma2(acc2[mp][j], am[mp], bd[j]);
        }
        __syncthreads();
    }

#pragma unroll
    for (int mp = 0; mp < 4; mp++) {
        float lo0, hi0, lo1, hi1, lo2, hi2, lo3, hi3;
        unpack2(lo0, hi0, acc2[mp][0]);
        unpack2(lo1, hi1, acc2[mp][1]);
        unpack2(lo2, hi2, acc2[mp][2]);
        unpack2(lo3, hi3, acc2[mp][3]);
        int m = m0 + ty * 8 + mp * 2;
        *(float4*)(g_FVt + (size_t)m * B_ + j0 + tx * 4)       = make_float4(lo0, lo1, lo2, lo3);
        *(float4*)(g_FVt + (size_t)(m + 1) * B_ + j0 + tx * 4) = make_float4(hi0, hi1, hi2, hi3);
    }
}

// ---------------------------------------------------------------------------
// 8 leaf weights (bits 0-2 free; bit3=half, bits 4-5=q), packed into 4 pairs
// ---------------------------------------------------------------------------
__device__ __forceinline__ void leaf8(const float h[6], int q, int half, u64 lp[4]) {
    float f3 = half    ? (1.0f - h[3]) : h[3];
    float f4 = (q & 1) ? (1.0f - h[4]) : h[4];
    float f5 = (q & 2) ? (1.0f - h[5]) : h[5];
    float pref = f4 * f5 * f3;
    float g0 = 1.0f - h[0], g1 = 1.0f - h[1], g2 = 1.0f - h[2];
    float l1_0 = pref * h[0], l1_1 = pref * g0;
    float l2_0 = l1_0 * h[1], l2_1 = l1_1 * h[1];
    float l2_2 = l1_0 * g1,   l2_3 = l1_1 * g1;
    lp[0] = pack2(l2_0 * h[2], l2_1 * h[2]);
    lp[1] = pack2(l2_2 * h[2], l2_3 * h[2]);
    lp[2] = pack2(l2_0 * g2,   l2_1 * g2);
    lp[3] = pack2(l2_2 * g2,   l2_3 * g2);
}

// ---------------------------------------------------------------------------
// Kernel C: thread = 2 batch rows (b, b+64) x 8 u's. ALL 4 resp tiles are
// staged up front behind ONE barrier; the main loop is barrier-free.
// Grid (8 b-groups of 128, 128 n-chunks of 4) = 1024 blocks, 128 threads.
// ---------------------------------------------------------------------------
__global__ void __launch_bounds__(128, 5) k_forest(const float* __restrict__ resp,
                                                   float* __restrict__ out) {
    __shared__ float resp_s[4][U_][L_];   // 16 KB: tiles for the 4 n's
    __shared__ float sc_s[24], of_s[24];

    int t   = threadIdx.x;
    int grp = t >> 6;          // 0: u 0-7, 1: u 8-15
    int bl  = t & 63;
    int bg  = blockIdx.x;      // 8 groups of 128 b
    int ng  = blockIdx.y;      // 128 chunks of 4 n
    int b0  = bg * 128 + bl;
    int b1  = b0 + 64;

    if (t < 24) { sc_s[t] = g_sc[ng * 24 + t]; of_s[t] = g_of[ng * 24 + t]; }
    {   // stage all 4 response tiles: 4096 floats = 1024 float4, 8 per thread
        const float4* src = (const float4*)(resp + (size_t)ng * 4 * (U_ * L_));
        float4* dst = (float4*)&resp_s[0][0][0];
#pragma unroll
        for (int j = 0; j < 8; j++) dst[t + j * 128] = src[t + j * 128];
    }
    __syncthreads();   // the ONLY barrier

    u64 acc[2][8];
#pragma unroll
    for (int r = 0; r < 2; r++)
#pragma unroll
        for (int j = 0; j < 8; j++) acc[r][j] = 0ull;

#pragma unroll
    for (int nl = 0; nl < 4; nl++) {
        int n = ng * 4 + nl;

        // sparsemoid bins for both rows — coalesced loads from FVt
        float h0[6], h1[6];
        const float* fvp = g_FVt + (size_t)n * 6 * B_;
#pragma unroll
        for (int d = 0; d < 6; d++) {
            float sc = sc_s[nl * 6 + d], of = of_s[nl * 6 + d];
            float v0 = fvp[(size_t)d * B_ + b0] * sc + of;
            float v1 = fvp[(size_t)d * B_ + b1] * sc + of;
            h0[d] = fminf(fmaxf(v0, 0.0f), 1.0f);
            h1[d] = fminf(fmaxf(v1, 0.0f), 1.0f);
        }

#pragma unroll
        for (int q = 0; q < 4; q++) {
#pragma unroll
            for (int half = 0; half < 2; half++) {
                u64 lp0[4], lp1[4];
                leaf8(h0, q, half, lp0);
                leaf8(h1, q, half, lp1);
                int cb = q * 16 + half * 8;

#pragma unroll
                for (int iup = 0; iup < 4; iup++) {
                    int ua = (grp << 3) + iup;
                    const double2* ra = (const double2*)&resp_s[nl][ua][cb];
                    const double2* rb = (const double2*)&resp_s[nl][ua + 4][cb];
                    double2 va0 = ra[0], va1 = ra[1];      // broadcast LDS.128
                    double2 vb0 = rb[0], vb1 = rb[1];
                    u64 a0 = d2l(va0.x), a1 = d2l(va0.y), a2 = d2l(va1.x), a3 = d2l(va1.y);
                    u64 c0 = d2l(vb0.x), c1 = d2l(vb0.y), c2 = d2l(vb1.x), c3 = d2l(vb1.y);
                    fma2(acc[0][iup],     lp0[0], a0);
                    fma2(acc[1][iup],     lp1[0], a0);
                    fma2(acc[0][iup + 4], lp0[0], c0);
                    fma2(acc[1][iup + 4], lp1[0], c0);
                    fma2(acc[0][iup],     lp0[1], a1);
                    fma2(acc[1][iup],     lp1[1], a1);
                    fma2(acc[0][iup + 4], lp0[1], c1);
                    fma2(acc[1][iup + 4], lp1[1], c1);
                    fma2(acc[0][iup],     lp0[2], a2);
                    fma2(acc[1][iup],     lp1[2], a2);
                    fma2(acc[0][iup + 4], lp0[2], c2);
                    fma2(acc[1][iup + 4], lp1[2], c2);
                    fma2(acc[0][iup],     lp0[3], a3);
                    fma2(acc[1][iup],     lp1[3], a3);
                    fma2(acc[0][iup + 4], lp0[3], c3);
                    fma2(acc[1][iup + 4], lp1[3], c3);
                }
            }
        }
    }

#pragma unroll
    for (int j = 0; j < 8; j++) {
        int u = (grp << 3) + j;
        float lo, hi;
        unpack2(lo, hi, acc[0][j]);
        atomicAdd(&out[b0 * U_ + u], lo + hi);
        unpack2(lo, hi, acc[1][j]);
        atomicAdd(&out[b1 * U_ + u], lo + hi);
    }
}

// ---------------------------------------------------------------------------
extern "C" void kernel_launch(void* const* d_in, const int* in_sizes, int n_in,
                              void* d_out, int out_size) {
    const float* x    = (const float*)d_in[0];  // [B, I]
    const float* fsl  = (const float*)d_in[1];  // [I, N, D]
    const float* th   = (const float*)d_in[2];  // [N, D]
    const float* lt   = (const float*)d_in[3];  // [N, D]
    const float* resp = (const float*)d_in[4];  // [N, U, 2^D]
    float* out = (float*)d_out;                 // [B, U]

    cudaMemsetAsync(out, 0, (size_t)B_ * U_ * sizeof(float), 0);

    k_sparsemax<<<(I_ * N_ + 255) / 256, 256>>>(fsl);
    k_scaleoff<<<(ND_ + 255) / 256, 256>>>(th, lt);
    k_gemm<<<dim3(B_ / 64, ND_ / 128), 256>>>(x);
    k_forest<<<dim3(B_ / 128, N_ / 4), 128>>>(resp, out);
}

// round 8
// speedup vs baseline: 1.3265x; 1.3265x over previous
#include <cuda_runtime.h>
#include <cstdint>

#define B_  1024
#define I_  256
#define N_  512
#define D_  6
#define U_  16
#define L_  64
#define ND_ (N_ * D_)   // 3072

__device__ float g_W  [I_ * ND_];   // sparsemax(feature_selection_logits), [I][ND]
__device__ float g_FVt[ND_ * B_];   // feature values TRANSPOSED, [ND][B]
__device__ float g_sc [ND_];        // 0.5*exp(-lt)
__device__ float g_of [ND_];        // 0.5 - th*0.5*exp(-lt)

typedef unsigned long long u64;

__device__ __forceinline__ void fma2(u64 &acc, u64 a, u64 b) {
    asm("fma.rn.f32x2 %0, %1, %2, %0;" : "+l"(acc) : "l"(a), "l"(b));
}
__device__ __forceinline__ u64 pack2(float lo, float hi) {
    u64 r; asm("mov.b64 %0, {%1, %2};" : "=l"(r) : "f"(lo), "f"(hi)); return r;
}
__device__ __forceinline__ void unpack2(float &lo, float &hi, u64 v) {
    asm("mov.b64 {%0, %1}, %2;" : "=f"(lo), "=f"(hi) : "l"(v));
}
__device__ __forceinline__ u64 d2l(double d) { return __double_as_longlong(d); }

__device__ __forceinline__ uint32_t tf32r(float x) {
    uint32_t r; asm("cvt.rna.tf32.f32 %0, %1;" : "=r"(r) : "f"(x)); return r;
}

// mma.sync m16n8k8 tf32: D = A*B + D (in place on C regs)
__device__ __forceinline__ void mma_tf32(float c[4], uint32_t a0, uint32_t a1,
                                         uint32_t a2, uint32_t a3,
                                         uint32_t b0, uint32_t b1) {
    asm volatile(
        "mma.sync.aligned.m16n8k8.row.col.f32.tf32.tf32.f32 "
        "{%0,%1,%2,%3}, {%4,%5,%6,%7}, {%8,%9}, {%0,%1,%2,%3};"
        : "+f"(c[0]), "+f"(c[1]), "+f"(c[2]), "+f"(c[3])
        : "r"(a0), "r"(a1), "r"(a2), "r"(a3), "r"(b0), "r"(b1));
}

// ---------------------------------------------------------------------------
// Kernel A: sparsemax over last axis (D=6) for each (i, n)
// ---------------------------------------------------------------------------
__global__ void k_sparsemax(const float* __restrict__ fsl) {
    int idx = blockIdx.x * blockDim.x + threadIdx.x;
    if (idx >= I_ * N_) return;
    const float* z = fsl + (size_t)idx * D_;
    float z0 = z[0], z1 = z[1], z2 = z[2], z3 = z[3], z4 = z[4], z5 = z[5];
    float s0 = z0, s1 = z1, s2 = z2, s3 = z3, s4 = z4, s5 = z5;

#define CSWP(a, b) { float _mx = fmaxf(a, b); float _mn = fminf(a, b); a = _mx; b = _mn; }
    CSWP(s1, s2) CSWP(s4, s5) CSWP(s0, s2) CSWP(s3, s5)
    CSWP(s0, s1) CSWP(s3, s4) CSWP(s2, s5) CSWP(s0, s3)
    CSWP(s1, s4) CSWP(s2, s4) CSWP(s1, s3) CSWP(s2, s3)
#undef CSWP

    float cs = s0; int k = 1; float ts = cs;
    cs += s1; if (1.0f + 2.0f * s1 > cs) { k = 2; ts = cs; }
    cs += s2; if (1.0f + 3.0f * s2 > cs) { k = 3; ts = cs; }
    cs += s3; if (1.0f + 4.0f * s3 > cs) { k = 4; ts = cs; }
    cs += s4; if (1.0f + 5.0f * s4 > cs) { k = 5; ts = cs; }
    cs += s5; if (1.0f + 6.0f * s5 > cs) { k = 6; ts = cs; }
    float tau = (ts - 1.0f) / (float)k;

    float* w = g_W + (size_t)idx * D_;
    w[0] = fmaxf(z0 - tau, 0.0f);
    w[1] = fmaxf(z1 - tau, 0.0f);
    w[2] = fmaxf(z2 - tau, 0.0f);
    w[3] = fmaxf(z3 - tau, 0.0f);
    w[4] = fmaxf(z4 - tau, 0.0f);
    w[5] = fmaxf(z5 - tau, 0.0f);
}

__global__ void k_scaleoff(const float* __restrict__ th, const float* __restrict__ lt) {
    int idx = blockIdx.x * blockDim.x + threadIdx.x;
    if (idx >= ND_) return;
    float s = 0.5f * expf(-lt[idx]);
    g_sc[idx] = s;
    g_of[idx] = 0.5f - th[idx] * s;
}

// ---------------------------------------------------------------------------
// Kernel B: FVt[m=nd][j=b] = sum_k W[k][m] * x[j][k]  (fp32 scalar, unchanged)
// ---------------------------------------------------------------------------
__global__ void __launch_bounds__(256, 2) k_gemm(const float* __restrict__ x) {
    __shared__ float As[16][128];   // [k][m]
    __shared__ float Bs[16][68];    // [k][j], padded

    int t  = threadIdx.x;
    int tx = t & 15;
    int ty = t >> 4;
    int j0 = blockIdx.x * 64;
    int m0 = blockIdx.y * 128;

    int ak = t >> 4, amc = (t & 15) * 8;
    int bj = t >> 2, bkq = (t & 3) * 4;
    const float* aBase = g_W + (size_t)ak * ND_ + m0 + amc;
    const float* bBase = x + (size_t)(j0 + bj) * I_ + bkq;

    u64 acc2[4][4];
#pragma unroll
    for (int i = 0; i < 4; i++)
#pragma unroll
        for (int j = 0; j < 4; j++) acc2[i][j] = 0ull;

    float4 pa0 = *(const float4*)(aBase);
    float4 pa1 = *(const float4*)(aBase + 4);
    float4 pb  = *(const float4*)(bBase);

    for (int kt = 0; kt < I_; kt += 16) {
        *(float4*)&As[ak][amc]     = pa0;
        *(float4*)&As[ak][amc + 4] = pa1;
        Bs[bkq + 0][bj] = pb.x; Bs[bkq + 1][bj] = pb.y;
        Bs[bkq + 2][bj] = pb.z; Bs[bkq + 3][bj] = pb.w;
        __syncthreads();

        if (kt + 16 < I_) {
            pa0 = *(const float4*)(aBase + (size_t)(kt + 16) * ND_);
            pa1 = *(const float4*)(aBase + (size_t)(kt + 16) * ND_ + 4);
            pb  = *(const float4*)(bBase + kt + 16);
        }

#pragma unroll
        for (int kk = 0; kk < 16; kk++) {
            double2 a01 = *(const double2*)&As[kk][ty * 8];
            double2 a23 = *(const double2*)&As[kk][ty * 8 + 4];
            float4  bv  = *(const float4*)&Bs[kk][tx * 4];
            u64 am[4] = { d2l(a01.x), d2l(a01.y), d2l(a23.x), d2l(a23.y) };
            u64 bd[4] = { pack2(bv.x, bv.x), pack2(bv.y, bv.y),
                          pack2(bv.z, bv.z), pack2(bv.w, bv.w) };
#pragma unroll
            for (int mp = 0; mp < 4; mp++)
#pragma unroll
                for (int j = 0; j < 4; j++) fma2(acc2[mp][j], am[mp], bd[j]);
        }
        __syncthreads();
    }

#pragma unroll
    for (int mp = 0; mp < 4; mp++) {
        float lo0, hi0, lo1, hi1, lo2, hi2, lo3, hi3;
        unpack2(lo0, hi0, acc2[mp][0]);
        unpack2(lo1, hi1, acc2[mp][1]);
        unpack2(lo2, hi2, acc2[mp][2]);
        unpack2(lo3, hi3, acc2[mp][3]);
        int m = m0 + ty * 8 + mp * 2;
        *(float4*)(g_FVt + (size_t)m * B_ + j0 + tx * 4)       = make_float4(lo0, lo1, lo2, lo3);
        *(float4*)(g_FVt + (size_t)(m + 1) * B_ + j0 + tx * 4) = make_float4(hi0, hi1, hi2, hi3);
    }
}

// ---------------------------------------------------------------------------
// Kernel C (tensor): out[b][u] += sum_n sum_c w[b][n][c] * resp[n][u][c]
// mma.sync m16n8k8 tf32. Per warp: 16 b-rows x 16 u. Leaf index c decomposes
// per lane (g = lane>>2, tig = lane&3):  c = 8*s + tig + 4*sigma
//   bits0-1 = tig  -> F01 = f0*f1        (per b-row)
//   bit2    = sigma (k-slot, pairs with b0/b1)
//   bits3-5 = s    (k-step)              -> S[s] = f3*f4*f5
// A-frag (L1 order): a0=(g,slot0) a1=(g+8,slot0) a2=(g,slot1) a3=(g+8,slot1)
// B-frag: b0=resp[u0+g][8s+tig], b1=resp[u0+g][8s+tig+4]
// C-frag: c0=(g, 2tig) c1=(g, 2tig+1) c2=(g+8, 2tig) c3=(g+8, 2tig+1)
// Grid (16 b-tiles of 64, 64 n-groups of 8) = 1024 blocks, 128 threads.
// ---------------------------------------------------------------------------
__global__ void __launch_bounds__(128, 6) k_forest(const float* __restrict__ resp,
                                                   float* __restrict__ out) {
    __shared__ uint32_t resp_s[8][U_][68];   // tf32 bits, padded to 68
    __shared__ float sc_s[48], of_s[48];

    int t    = threadIdx.x;
    int w    = t >> 5;
    int lane = t & 31;
    int g    = lane >> 2;
    int tig  = lane & 3;
    int bt   = blockIdx.x;   // 16 b-tiles of 64
    int ng   = blockIdx.y;   // 64 n-groups of 8

    if (t < 48) { sc_s[t] = g_sc[ng * 48 + t]; of_s[t] = g_of[ng * 48 + t]; }

    {   // stage 8 response tiles (8192 floats), cvt to tf32
        const float4* src = (const float4*)(resp + (size_t)ng * 8 * (U_ * L_));
#pragma unroll
        for (int j = 0; j < 16; j++) {
            int idx = t + j * 128;           // float4 index in [0,2048)
            float4 v = src[idx];
            int fi = idx * 4;
            int nl = fi >> 10, rem = fi & 1023;
            uint32_t* dst = &resp_s[nl][rem >> 6][rem & 63];
            dst[0] = tf32r(v.x); dst[1] = tf32r(v.y);
            dst[2] = tf32r(v.z); dst[3] = tf32r(v.w);
        }
    }
    __syncthreads();

    float acc[2][4] = {};           // [n-rep(u half)][c-frag]
    int b_r0 = bt * 64 + w * 16 + g;     // rows b_r0, b_r0+8

    for (int nl = 0; nl < 8; nl++) {
        int n = ng * 8 + nl;
        const float* fvp = g_FVt + (size_t)n * 6 * B_;

        float h0[6], h1[6];
#pragma unroll
        for (int d = 0; d < 6; d++) {
            float sc = sc_s[nl * 6 + d], of = of_s[nl * 6 + d];
            float v0 = fvp[(size_t)d * B_ + b_r0]     * sc + of;
            float v1 = fvp[(size_t)d * B_ + b_r0 + 8] * sc + of;
            h0[d] = fminf(fmaxf(v0, 0.0f), 1.0f);
            h1[d] = fminf(fmaxf(v1, 0.0f), 1.0f);
        }

        // F01 per row (bits 0-1 of c are tig)
        float f0a = (tig & 1) ? (1.0f - h0[0]) : h0[0];
        float f0b = (tig & 1) ? (1.0f - h1[0]) : h1[0];
        float f1a = (tig & 2) ? (1.0f - h0[1]) : h0[1];
        float f1b = (tig & 2) ? (1.0f - h1[1]) : h1[1];
        float F0 = f0a * f1a, F1 = f0b * f1b;
        // slot factors (bit2 of c)
        float A00 = F0 * h0[2], A01 = F0 * (1.0f - h0[2]);   // row g:   slot0, slot1
        float A10 = F1 * h1[2], A11 = F1 * (1.0f - h1[2]);   // row g+8: slot0, slot1

        // S[s] = f3(s&1)*f4(s>>1&1)*f5(s>>2), per row
        float S0[8], S1[8];
        {
            float p0 = h0[3], p1 = 1.0f - h0[3];
            float r0 = h0[4], r1 = 1.0f - h0[4];
            float q0 = p0 * r0, q1 = p1 * r0, q2 = p0 * r1, q3 = p1 * r1;
            float t5 = h0[5], u5 = 1.0f - h0[5];
            S0[0] = q0 * t5; S0[1] = q1 * t5; S0[2] = q2 * t5; S0[3] = q3 * t5;
            S0[4] = q0 * u5; S0[5] = q1 * u5; S0[6] = q2 * u5; S0[7] = q3 * u5;
        }
        {
            float p0 = h1[3], p1 = 1.0f - h1[3];
            float r0 = h1[4], r1 = 1.0f - h1[4];
            float q0 = p0 * r0, q1 = p1 * r0, q2 = p0 * r1, q3 = p1 * r1;
            float t5 = h1[5], u5 = 1.0f - h1[5];
            S1[0] = q0 * t5; S1[1] = q1 * t5; S1[2] = q2 * t5; S1[3] = q3 * t5;
            S1[4] = q0 * u5; S1[5] = q1 * u5; S1[6] = q2 * u5; S1[7] = q3 * u5;
        }

#pragma unroll
        for (int s = 0; s < 8; s++) {
            uint32_t a0 = __float_as_uint(A00 * S0[s]);   // (g,    slot0)
            uint32_t a1 = __float_as_uint(A10 * S1[s]);   // (g+8,  slot0)
            uint32_t a2 = __float_as_uint(A01 * S0[s]);   // (g,    slot1)
            uint32_t a3 = __float_as_uint(A11 * S1[s]);   // (g+8,  slot1)
#pragma unroll
            for (int nr = 0; nr < 2; nr++) {
                uint32_t b0 = resp_s[nl][nr * 8 + g][8 * s + tig];
                uint32_t b1 = resp_s[nl][nr * 8 + g][8 * s + tig + 4];
                mma_tf32(acc[nr], a0, a1, a2, a3, b0, b1);
            }
        }
    }

    // epilogue: c0=(g,2tig) c1=(g,2tig+1) c2=(g+8,2tig) c3=(g+8,2tig+1)
#pragma unroll
    for (int nr = 0; nr < 2; nr++) {
        int u = nr * 8 + 2 * tig;
        atomicAdd(&out[b_r0 * U_ + u],           acc[nr][0]);
        atomicAdd(&out[b_r0 * U_ + u + 1],       acc[nr][1]);
        atomicAdd(&out[(b_r0 + 8) * U_ + u],     acc[nr][2]);
        atomicAdd(&out[(b_r0 + 8) * U_ + u + 1], acc[nr][3]);
    }
}

// ---------------------------------------------------------------------------
extern "C" void kernel_launch(void* const* d_in, const int* in_sizes, int n_in,
                              void* d_out, int out_size) {
    const float* x    = (const float*)d_in[0];  // [B, I]
    const float* fsl  = (const float*)d_in[1];  // [I, N, D]
    const float* th   = (const float*)d_in[2];  // [N, D]
    const float* lt   = (const float*)d_in[3];  // [N, D]
    const float* resp = (const float*)d_in[4];  // [N, U, 2^D]
    float* out = (float*)d_out;                 // [B, U]

    cudaMemsetAsync(out, 0, (size_t)B_ * U_ * sizeof(float), 0);

    k_sparsemax<<<(I_ * N_ + 255) / 256, 256>>>(fsl);
    k_scaleoff<<<(ND_ + 255) / 256, 256>>>(th, lt);
    k_gemm<<<dim3(B_ / 64, ND_ / 128), 256>>>(x);
    k_forest<<<dim3(B_ / 64, N_ / 8), 128>>>(resp, out);
}

// round 9
// speedup vs baseline: 1.8122x; 1.3662x over previous
#include <cuda_runtime.h>
#include <cuda_bf16.h>
#include <cstdint>

#define B_  1024
#define I_  256
#define N_  512
#define D_  6
#define U_  16
#define L_  64
#define ND_ (N_ * D_)   // 3072

__device__ float g_W  [I_ * ND_];            // sparsemax weights, [k=I][m=ND]
__device__ __nv_bfloat16 g_Wh[ND_ * I_];     // W transposed hi, [m][k]
__device__ __nv_bfloat16 g_Wl[ND_ * I_];     // W transposed lo, [m][k]
__device__ __nv_bfloat16 g_xh[B_ * I_];      // x hi, [j][k]
__device__ __nv_bfloat16 g_xl[B_ * I_];      // x lo, [j][k]
__device__ float g_FVt[ND_ * B_];            // feature values transposed, [m][j]
__device__ float g_sc [ND_];                 // 0.5*exp(-lt)
__device__ float g_of [ND_];                 // 0.5 - th*0.5*exp(-lt)

__device__ __forceinline__ uint32_t tf32r(float x) {
    uint32_t r; asm("cvt.rna.tf32.f32 %0, %1;" : "=r"(r) : "f"(x)); return r;
}

__device__ __forceinline__ void mma_tf32(float c[4], uint32_t a0, uint32_t a1,
                                         uint32_t a2, uint32_t a3,
                                         uint32_t b0, uint32_t b1) {
    asm volatile(
        "mma.sync.aligned.m16n8k8.row.col.f32.tf32.tf32.f32 "
        "{%0,%1,%2,%3}, {%4,%5,%6,%7}, {%8,%9}, {%0,%1,%2,%3};"
        : "+f"(c[0]), "+f"(c[1]), "+f"(c[2]), "+f"(c[3])
        : "r"(a0), "r"(a1), "r"(a2), "r"(a3), "r"(b0), "r"(b1));
}

__device__ __forceinline__ void mma_bf16(float c[4], uint32_t a0, uint32_t a1,
                                         uint32_t a2, uint32_t a3,
                                         uint32_t b0, uint32_t b1) {
    asm volatile(
        "mma.sync.aligned.m16n8k16.row.col.f32.bf16.bf16.f32 "
        "{%0,%1,%2,%3}, {%4,%5,%6,%7}, {%8,%9}, {%0,%1,%2,%3};"
        : "+f"(c[0]), "+f"(c[1]), "+f"(c[2]), "+f"(c[3])
        : "r"(a0), "r"(a1), "r"(a2), "r"(a3), "r"(b0), "r"(b1));
}

// ---------------------------------------------------------------------------
// Kernel P: fused prep. 512 blocks x 256 threads.
//   all 131072 threads: sparsemax over D=6 for one (i,n)
//   gt < 65536       : bf16 hi/lo split of x (float4 granularity)
//   gt < 3072        : scale/offset for the sparsemoid
// ---------------------------------------------------------------------------
__global__ void k_prep(const float* __restrict__ fsl,
                       const float* __restrict__ x,
                       const float* __restrict__ th,
                       const float* __restrict__ lt) {
    int gt = blockIdx.x * blockDim.x + threadIdx.x;

    {   // sparsemax for (i,n) = gt
        const float* z = fsl + (size_t)gt * D_;
        float z0 = z[0], z1 = z[1], z2 = z[2], z3 = z[3], z4 = z[4], z5 = z[5];
        float s0 = z0, s1 = z1, s2 = z2, s3 = z3, s4 = z4, s5 = z5;
#define CSWP(a, b) { float _mx = fmaxf(a, b); float _mn = fminf(a, b); a = _mx; b = _mn; }
        CSWP(s1, s2) CSWP(s4, s5) CSWP(s0, s2) CSWP(s3, s5)
        CSWP(s0, s1) CSWP(s3, s4) CSWP(s2, s5) CSWP(s0, s3)
        CSWP(s1, s4) CSWP(s2, s4) CSWP(s1, s3) CSWP(s2, s3)
#undef CSWP
        float cs = s0; int k = 1; float ts = cs;
        cs += s1; if (1.0f + 2.0f * s1 > cs) { k = 2; ts = cs; }
        cs += s2; if (1.0f + 3.0f * s2 > cs) { k = 3; ts = cs; }
        cs += s3; if (1.0f + 4.0f * s3 > cs) { k = 4; ts = cs; }
        cs += s4; if (1.0f + 5.0f * s4 > cs) { k = 5; ts = cs; }
        cs += s5; if (1.0f + 6.0f * s5 > cs) { k = 6; ts = cs; }
        float tau = (ts - 1.0f) / (float)k;

        float* w = g_W + (size_t)gt * D_;
        w[0] = fmaxf(z0 - tau, 0.0f);
        w[1] = fmaxf(z1 - tau, 0.0f);
        w[2] = fmaxf(z2 - tau, 0.0f);
        w[3] = fmaxf(z3 - tau, 0.0f);
        w[4] = fmaxf(z4 - tau, 0.0f);
        w[5] = fmaxf(z5 - tau, 0.0f);
    }

    if (gt < (B_ * I_) / 4) {   // x split, 4 elements per thread
        float4 v = ((const float4*)x)[gt];
        float f[4] = { v.x, v.y, v.z, v.w };
        __nv_bfloat16 h[4], l[4];
#pragma unroll
        for (int i = 0; i < 4; i++) {
            h[i] = __float2bfloat16_rn(f[i]);
            l[i] = __float2bfloat16_rn(f[i] - __bfloat162float(h[i]));
        }
        __nv_bfloat162 h01(h[0], h[1]), h23(h[2], h[3]);
        __nv_bfloat162 l01(l[0], l[1]), l23(l[2], l[3]);
        uint2 uh = make_uint2(*reinterpret_cast<uint32_t*>(&h01),
                              *reinterpret_cast<uint32_t*>(&h23));
        uint2 ul = make_uint2(*reinterpret_cast<uint32_t*>(&l01),
                              *reinterpret_cast<uint32_t*>(&l23));
        *(uint2*)(g_xh + (size_t)gt * 4) = uh;
        *(uint2*)(g_xl + (size_t)gt * 4) = ul;
    }

    if (gt < ND_) {   // scale/offset
        float s = 0.5f * expf(-lt[gt]);
        g_sc[gt] = s;
        g_of[gt] = 0.5f - th[gt] * s;
    }
}

// ---------------------------------------------------------------------------
// Kernel T: transpose + bf16 split of W:  g_Wh/g_Wl[m][k] = split(g_W[k][m])
// 32x32 tiles, grid (96 m-tiles, 8 k-tiles), 256 threads.
// ---------------------------------------------------------------------------
__global__ void k_wsplit() {
    __shared__ float s[32][33];
    int t  = threadIdx.x;
    int m0 = blockIdx.x * 32;
    int k0 = blockIdx.y * 32;
    int r  = t >> 5, c = t & 31;

#pragma unroll
    for (int i = 0; i < 4; i++)
        s[r + i * 8][c] = g_W[(size_t)(k0 + r + i * 8) * ND_ + m0 + c];
    __syncthreads();

#pragma unroll
    for (int i = 0; i < 4; i++) {
        int r2 = r + i * 8;
        float v = s[c][r2];
        __nv_bfloat16 hi = __float2bfloat16_rn(v);
        __nv_bfloat16 lo = __float2bfloat16_rn(v - __bfloat162float(hi));
        g_Wh[(size_t)(m0 + r2) * I_ + k0 + c] = hi;
        g_Wl[(size_t)(m0 + r2) * I_ + k0 + c] = lo;
    }
}

// ---------------------------------------------------------------------------
// Kernel B: tensor GEMM  FVt[m][j] = sum_k W^T[m][k] * x[j][k]
// bf16 3-term split (Ah*Bh + Al*Bh + Ah*Bl), mma.sync m16n8k16.
// Block: 256 thr (8 warps), tile M=128 (nd) x J=64 (b), K-chunks of 64.
// Warp w owns m-frag w (16 rows) x all 64 j (8 B-frags).
// smem rows padded to 72 bf16 -> conflict-free 4B frag LDS.
// ---------------------------------------------------------------------------
__global__ void __launch_bounds__(256) k_gemm() {
    __shared__ __nv_bfloat16 Wh_s[128][72], Wl_s[128][72];
    __shared__ __nv_bfloat16 Xh_s[64][72],  Xl_s[64][72];

    int t    = threadIdx.x;
    int w    = t >> 5;
    int lane = t & 31;
    int g    = lane >> 2;
    int tig  = lane & 3;
    int jt   = blockIdx.x;   // 16 j-tiles of 64
    int mt   = blockIdx.y;   // 24 m-tiles of 128

    float acc[8][4];
#pragma unroll
    for (int jf = 0; jf < 8; jf++)
#pragma unroll
        for (int i = 0; i < 4; i++) acc[jf][i] = 0.0f;

    for (int kc = 0; kc < I_; kc += 64) {
        __syncthreads();   // previous chunk's readers done
        {   // stage W tiles: 128 rows x 64 k, 8 uint4 segs per row, x2 matrices
#pragma unroll
            for (int i = 0; i < 4; i++) {
                int idx = t + i * 256;          // 0..1023
                int row = idx >> 3, seg = idx & 7;
                size_t go = (size_t)(mt * 128 + row) * I_ + kc + seg * 8;
                *(uint4*)&Wh_s[row][seg * 8] = *(const uint4*)(g_Wh + go);
                *(uint4*)&Wl_s[row][seg * 8] = *(const uint4*)(g_Wl + go);
            }
            // stage x tiles: 64 rows x 64 k
#pragma unroll
            for (int i = 0; i < 2; i++) {
                int idx = t + i * 256;          // 0..511
                int row = idx >> 3, seg = idx & 7;
                size_t go = (size_t)(jt * 64 + row) * I_ + kc + seg * 8;
                *(uint4*)&Xh_s[row][seg * 8] = *(const uint4*)(g_xh + go);
                *(uint4*)&Xl_s[row][seg * 8] = *(const uint4*)(g_xl + go);
            }
        }
        __syncthreads();

#pragma unroll
        for (int kst = 0; kst < 4; kst++) {
            int k0 = kst * 16 + 2 * tig;
            uint32_t ah0 = *(uint32_t*)&Wh_s[w * 16 + g][k0];
            uint32_t ah1 = *(uint32_t*)&Wh_s[w * 16 + g + 8][k0];
            uint32_t ah2 = *(uint32_t*)&Wh_s[w * 16 + g][k0 + 8];
            uint32_t ah3 = *(uint32_t*)&Wh_s[w * 16 + g + 8][k0 + 8];
            uint32_t al0 = *(uint32_t*)&Wl_s[w * 16 + g][k0];
            uint32_t al1 = *(uint32_t*)&Wl_s[w * 16 + g + 8][k0];
            uint32_t al2 = *(uint32_t*)&Wl_s[w * 16 + g][k0 + 8];
            uint32_t al3 = *(uint32_t*)&Wl_s[w * 16 + g + 8][k0 + 8];

#pragma unroll
            for (int jf = 0; jf < 8; jf++) {
                uint32_t bh0 = *(uint32_t*)&Xh_s[jf * 8 + g][k0];
                uint32_t bh1 = *(uint32_t*)&Xh_s[jf * 8 + g][k0 + 8];
                uint32_t bl0 = *(uint32_t*)&Xl_s[jf * 8 + g][k0];
                uint32_t bl1 = *(uint32_t*)&Xl_s[jf * 8 + g][k0 + 8];
                mma_bf16(acc[jf], ah0, ah1, ah2, ah3, bh0, bh1);
                mma_bf16(acc[jf], al0, al1, al2, al3, bh0, bh1);
                mma_bf16(acc[jf], ah0, ah1, ah2, ah3, bl0, bl1);
            }
        }
    }

    int m0 = mt * 128 + w * 16;
#pragma unroll
    for (int jf = 0; jf < 8; jf++) {
        int j = jt * 64 + jf * 8 + 2 * tig;
        *(float2*)&g_FVt[(size_t)(m0 + g) * B_ + j]     = make_float2(acc[jf][0], acc[jf][1]);
        *(float2*)&g_FVt[(size_t)(m0 + g + 8) * B_ + j] = make_float2(acc[jf][2], acc[jf][3]);
    }
}

// ---------------------------------------------------------------------------
// Kernel C (tensor forest, unchanged from R8): mma m16n8k8 tf32.
// ---------------------------------------------------------------------------
__global__ void __launch_bounds__(128, 6) k_forest(const float* __restrict__ resp,
                                                   float* __restrict__ out) {
    __shared__ uint32_t resp_s[8][U_][68];   // tf32 bits, padded
    __shared__ float sc_s[48], of_s[48];

    int t    = threadIdx.x;
    int w    = t >> 5;
    int lane = t & 31;
    int g    = lane >> 2;
    int tig  = lane & 3;
    int bt   = blockIdx.x;   // 16 b-tiles of 64
    int ng   = blockIdx.y;   // 64 n-groups of 8

    if (t < 48) { sc_s[t] = g_sc[ng * 48 + t]; of_s[t] = g_of[ng * 48 + t]; }

    {   // stage 8 response tiles, cvt to tf32
        const float4* src = (const float4*)(resp + (size_t)ng * 8 * (U_ * L_));
#pragma unroll
        for (int j = 0; j < 16; j++) {
            int idx = t + j * 128;
            float4 v = src[idx];
            int fi = idx * 4;
            int nl = fi >> 10, rem = fi & 1023;
            uint32_t* dst = &resp_s[nl][rem >> 6][rem & 63];
            dst[0] = tf32r(v.x); dst[1] = tf32r(v.y);
            dst[2] = tf32r(v.z); dst[3] = tf32r(v.w);
        }
    }
    __syncthreads();

    float acc[2][4] = {};
    int b_r0 = bt * 64 + w * 16 + g;

    for (int nl = 0; nl < 8; nl++) {
        int n = ng * 8 + nl;
        const float* fvp = g_FVt + (size_t)n * 6 * B_;

        float h0[6], h1[6];
#pragma unroll
        for (int d = 0; d < 6; d++) {
            float sc = sc_s[nl * 6 + d], of = of_s[nl * 6 + d];
            float v0 = fvp[(size_t)d * B_ + b_r0]     * sc + of;
            float v1 = fvp[(size_t)d * B_ + b_r0 + 8] * sc + of;
            h0[d] = fminf(fmaxf(v0, 0.0f), 1.0f);
            h1[d] = fminf(fmaxf(v1, 0.0f), 1.0f);
        }

        float f0a = (tig & 1) ? (1.0f - h0[0]) : h0[0];
        float f0b = (tig & 1) ? (1.0f - h1[0]) : h1[0];
        float f1a = (tig & 2) ? (1.0f - h0[1]) : h0[1];
        float f1b = (tig & 2) ? (1.0f - h1[1]) : h1[1];
        float F0 = f0a * f1a, F1 = f0b * f1b;
        float A00 = F0 * h0[2], A01 = F0 * (1.0f - h0[2]);
        float A10 = F1 * h1[2], A11 = F1 * (1.0f - h1[2]);

        float S0[8], S1[8];
        {
            float p0 = h0[3], p1 = 1.0f - h0[3];
            float r0 = h0[4], r1 = 1.0f - h0[4];
            float q0 = p0 * r0, q1 = p1 * r0, q2 = p0 * r1, q3 = p1 * r1;
            float t5 = h0[5], u5 = 1.0f - h0[5];
            S0[0] = q0 * t5; S0[1] = q1 * t5; S0[2] = q2 * t5; S0[3] = q3 * t5;
            S0[4] = q0 * u5; S0[5] = q1 * u5; S0[6] = q2 * u5; S0[7] = q3 * u5;
        }
        {
            float p0 = h1[3], p1 = 1.0f - h1[3];
            float r0 = h1[4], r1 = 1.0f - h1[4];
            float q0 = p0 * r0, q1 = p1 * r0, q2 = p0 * r1, q3 = p1 * r1;
            float t5 = h1[5], u5 = 1.0f - h1[5];
            S1[0] = q0 * t5; S1[1] = q1 * t5; S1[2] = q2 * t5; S1[3] = q3 * t5;
            S1[4] = q0 * u5; S1[5] = q1 * u5; S1[6] = q2 * u5; S1[7] = q3 * u5;
        }

#pragma unroll
        for (int s = 0; s < 8; s++) {
            uint32_t a0 = __float_as_uint(A00 * S0[s]);
            uint32_t a1 = __float_as_uint(A10 * S1[s]);
            uint32_t a2 = __float_as_uint(A01 * S0[s]);
            uint32_t a3 = __float_as_uint(A11 * S1[s]);
#pragma unroll
            for (int nr = 0; nr < 2; nr++) {
                uint32_t b0 = resp_s[nl][nr * 8 + g][8 * s + tig];
                uint32_t b1 = resp_s[nl][nr * 8 + g][8 * s + tig + 4];
                mma_tf32(acc[nr], a0, a1, a2, a3, b0, b1);
            }
        }
    }

#pragma unroll
    for (int nr = 0; nr < 2; nr++) {
        int u = nr * 8 + 2 * tig;
        atomicAdd(&out[b_r0 * U_ + u],           acc[nr][0]);
        atomicAdd(&out[b_r0 * U_ + u + 1],       acc[nr][1]);
        atomicAdd(&out[(b_r0 + 8) * U_ + u],     acc[nr][2]);
        atomicAdd(&out[(b_r0 + 8) * U_ + u + 1], acc[nr][3]);
    }
}

// ---------------------------------------------------------------------------
extern "C" void kernel_launch(void* const* d_in, const int* in_sizes, int n_in,
                              void* d_out, int out_size) {
    const float* x    = (const float*)d_in[0];  // [B, I]
    const float* fsl  = (const float*)d_in[1];  // [I, N, D]
    const float* th   = (const float*)d_in[2];  // [N, D]
    const float* lt   = (const float*)d_in[3];  // [N, D]
    const float* resp = (const float*)d_in[4];  // [N, U, 2^D]
    float* out = (float*)d_out;                 // [B, U]

    cudaMemsetAsync(out, 0, (size_t)B_ * U_ * sizeof(float), 0);

    k_prep<<<512, 256>>>(fsl, x, th, lt);
    k_wsplit<<<dim3(ND_ / 32, I_ / 32), 256>>>();
    k_gemm<<<dim3(B_ / 64, ND_ / 128), 256>>>();
    k_forest<<<dim3(B_ / 64, N_ / 8), 128>>>(resp, out);
}

// round 10
// speedup vs baseline: 1.9001x; 1.0485x over previous
#include <cuda_runtime.h>
#include <cuda_bf16.h>
#include <cstdint>

#define B_  1024
#define I_  256
#define N_  512
#define D_  6
#define U_  16
#define L_  64
#define ND_ (N_ * D_)   // 3072

__device__ float g_W  [I_ * ND_];            // sparsemax weights, [k=I][m=ND]
__device__ __nv_bfloat16 g_Wh[ND_ * I_];     // W transposed hi, [m][k]
__device__ __nv_bfloat16 g_Wl[ND_ * I_];     // W transposed lo, [m][k]
__device__ __nv_bfloat16 g_xh[B_ * I_];      // x hi, [j][k]
__device__ __nv_bfloat16 g_xl[B_ * I_];      // x lo, [j][k]
__device__ float g_FVt[ND_ * B_];            // feature values transposed, [m][j]
__device__ float g_sc [ND_];                 // 0.5*exp(-lt)
__device__ float g_of [ND_];                 // 0.5 - th*0.5*exp(-lt)
__device__ uint32_t g_respP[N_ * U_ * L_];   // resp, tf32 bits, pair-interleaved cols

__device__ __forceinline__ uint32_t tf32r(float x) {
    uint32_t r; asm("cvt.rna.tf32.f32 %0, %1;" : "=r"(r) : "f"(x)); return r;
}

__device__ __forceinline__ void mma_tf32(float c[4], uint32_t a0, uint32_t a1,
                                         uint32_t a2, uint32_t a3,
                                         uint32_t b0, uint32_t b1) {
    asm volatile(
        "mma.sync.aligned.m16n8k8.row.col.f32.tf32.tf32.f32 "
        "{%0,%1,%2,%3}, {%4,%5,%6,%7}, {%8,%9}, {%0,%1,%2,%3};"
        : "+f"(c[0]), "+f"(c[1]), "+f"(c[2]), "+f"(c[3])
        : "r"(a0), "r"(a1), "r"(a2), "r"(a3), "r"(b0), "r"(b1));
}

__device__ __forceinline__ void mma_bf16(float c[4], uint32_t a0, uint32_t a1,
                                         uint32_t a2, uint32_t a3,
                                         uint32_t b0, uint32_t b1) {
    asm volatile(
        "mma.sync.aligned.m16n8k16.row.col.f32.bf16.bf16.f32 "
        "{%0,%1,%2,%3}, {%4,%5,%6,%7}, {%8,%9}, {%0,%1,%2,%3};"
        : "+f"(c[0]), "+f"(c[1]), "+f"(c[2]), "+f"(c[3])
        : "r"(a0), "r"(a1), "r"(a2), "r"(a3), "r"(b0), "r"(b1));
}

// ---------------------------------------------------------------------------
// Kernel P: fused prep. 512 blocks x 256 threads (gt in [0,131072)).
//   all threads : sparsemax over D=6 for one (i,n)
//   all threads : convert ONE float4 of resp -> tf32, pair-interleaved layout
//   gt < 65536  : bf16 hi/lo split of x
//   gt < 3072   : scale/offset for the sparsemoid
// ---------------------------------------------------------------------------
__global__ void k_prep(const float* __restrict__ fsl,
                       const float* __restrict__ x,
                       const float* __restrict__ th,
                       const float* __restrict__ lt,
                       const float* __restrict__ resp) {
    int gt = blockIdx.x * blockDim.x + threadIdx.x;

    {   // sparsemax for (i,n) = gt
        const float* z = fsl + (size_t)gt * D_;
        float z0 = z[0], z1 = z[1], z2 = z[2], z3 = z[3], z4 = z[4], z5 = z[5];
        float s0 = z0, s1 = z1, s2 = z2, s3 = z3, s4 = z4, s5 = z5;
#define CSWP(a, b) { float _mx = fmaxf(a, b); float _mn = fminf(a, b); a = _mx; b = _mn; }
        CSWP(s1, s2) CSWP(s4, s5) CSWP(s0, s2) CSWP(s3, s5)
        CSWP(s0, s1) CSWP(s3, s4) CSWP(s2, s5) CSWP(s0, s3)
        CSWP(s1, s4) CSWP(s2, s4) CSWP(s1, s3) CSWP(s2, s3)
#undef CSWP
        float cs = s0; int k = 1; float ts = cs;
        cs += s1; if (1.0f + 2.0f * s1 > cs) { k = 2; ts = cs; }
        cs += s2; if (1.0f + 3.0f * s2 > cs) { k = 3; ts = cs; }
        cs += s3; if (1.0f + 4.0f * s3 > cs) { k = 4; ts = cs; }
        cs += s4; if (1.0f + 5.0f * s4 > cs) { k = 5; ts = cs; }
        cs += s5; if (1.0f + 6.0f * s5 > cs) { k = 6; ts = cs; }
        float tau = (ts - 1.0f) / (float)k;

        float* w = g_W + (size_t)gt * D_;
        w[0] = fmaxf(z0 - tau, 0.0f);
        w[1] = fmaxf(z1 - tau, 0.0f);
        w[2] = fmaxf(z2 - tau, 0.0f);
        w[3] = fmaxf(z3 - tau, 0.0f);
        w[4] = fmaxf(z4 - tau, 0.0f);
        w[5] = fmaxf(z5 - tau, 0.0f);
    }

    {   // resp -> tf32, pair-interleaved: col'(c) = 8*(c>>3) + 2*(c&3) + ((c>>2)&1)
        float4 v = ((const float4*)resp)[gt];    // covers c4 = gt*4 (same s, sigma)
        int fi  = gt * 4;
        int nu  = fi >> 6;            // n*16 + u
        int c4  = fi & 63;
        int s   = c4 >> 3;
        int sig = (c4 >> 2) & 1;
        uint32_t* dst = g_respP + (size_t)nu * 64 + 8 * s + sig;
        dst[0] = tf32r(v.x);          // tig 0
        dst[2] = tf32r(v.y);          // tig 1
        dst[4] = tf32r(v.z);          // tig 2
        dst[6] = tf32r(v.w);          // tig 3
    }

    if (gt < (B_ * I_) / 4) {   // x split, 4 elements per thread
        float4 v = ((const float4*)x)[gt];
        float f[4] = { v.x, v.y, v.z, v.w };
        __nv_bfloat16 h[4], l[4];
#pragma unroll
        for (int i = 0; i < 4; i++) {
            h[i] = __float2bfloat16_rn(f[i]);
            l[i] = __float2bfloat16_rn(f[i] - __bfloat162float(h[i]));
        }
        __nv_bfloat162 h01(h[0], h[1]), h23(h[2], h[3]);
        __nv_bfloat162 l01(l[0], l[1]), l23(l[2], l[3]);
        uint2 uh = make_uint2(*reinterpret_cast<uint32_t*>(&h01),
                              *reinterpret_cast<uint32_t*>(&h23));
        uint2 ul = make_uint2(*reinterpret_cast<uint32_t*>(&l01),
                              *reinterpret_cast<uint32_t*>(&l23));
        *(uint2*)(g_xh + (size_t)gt * 4) = uh;
        *(uint2*)(g_xl + (size_t)gt * 4) = ul;
    }

    if (gt < ND_) {   // scale/offset
        float s = 0.5f * expf(-lt[gt]);
        g_sc[gt] = s;
        g_of[gt] = 0.5f - th[gt] * s;
    }
}

// ---------------------------------------------------------------------------
// Kernel T: transpose + bf16 split of W
// ---------------------------------------------------------------------------
__global__ void k_wsplit() {
    __shared__ float s[32][33];
    int t  = threadIdx.x;
    int m0 = blockIdx.x * 32;
    int k0 = blockIdx.y * 32;
    int r  = t >> 5, c = t & 31;

#pragma unroll
    for (int i = 0; i < 4; i++)
        s[r + i * 8][c] = g_W[(size_t)(k0 + r + i * 8) * ND_ + m0 + c];
    __syncthreads();

#pragma unroll
    for (int i = 0; i < 4; i++) {
        int r2 = r + i * 8;
        float v = s[c][r2];
        __nv_bfloat16 hi = __float2bfloat16_rn(v);
        __nv_bfloat16 lo = __float2bfloat16_rn(v - __bfloat162float(hi));
        g_Wh[(size_t)(m0 + r2) * I_ + k0 + c] = hi;
        g_Wl[(size_t)(m0 + r2) * I_ + k0 + c] = lo;
    }
}

// ---------------------------------------------------------------------------
// Kernel B: tensor GEMM (unchanged from R9)
// ---------------------------------------------------------------------------
__global__ void __launch_bounds__(256) k_gemm() {
    __shared__ __nv_bfloat16 Wh_s[128][72], Wl_s[128][72];
    __shared__ __nv_bfloat16 Xh_s[64][72],  Xl_s[64][72];

    int t    = threadIdx.x;
    int w    = t >> 5;
    int lane = t & 31;
    int g    = lane >> 2;
    int tig  = lane & 3;
    int jt   = blockIdx.x;
    int mt   = blockIdx.y;

    float acc[8][4];
#pragma unroll
    for (int jf = 0; jf < 8; jf++)
#pragma unroll
        for (int i = 0; i < 4; i++) acc[jf][i] = 0.0f;

    for (int kc = 0; kc < I_; kc += 64) {
        __syncthreads();
        {
#pragma unroll
            for (int i = 0; i < 4; i++) {
                int idx = t + i * 256;
                int row = idx >> 3, seg = idx & 7;
                size_t go = (size_t)(mt * 128 + row) * I_ + kc + seg * 8;
                *(uint4*)&Wh_s[row][seg * 8] = *(const uint4*)(g_Wh + go);
                *(uint4*)&Wl_s[row][seg * 8] = *(const uint4*)(g_Wl + go);
            }
#pragma unroll
            for (int i = 0; i < 2; i++) {
                int idx = t + i * 256;
                int row = idx >> 3, seg = idx & 7;
                size_t go = (size_t)(jt * 64 + row) * I_ + kc + seg * 8;
                *(uint4*)&Xh_s[row][seg * 8] = *(const uint4*)(g_xh + go);
                *(uint4*)&Xl_s[row][seg * 8] = *(const uint4*)(g_xl + go);
            }
        }
        __syncthreads();

#pragma unroll
        for (int kst = 0; kst < 4; kst++) {
            int k0 = kst * 16 + 2 * tig;
            uint32_t ah0 = *(uint32_t*)&Wh_s[w * 16 + g][k0];
            uint32_t ah1 = *(uint32_t*)&Wh_s[w * 16 + g + 8][k0];
            uint32_t ah2 = *(uint32_t*)&Wh_s[w * 16 + g][k0 + 8];
            uint32_t ah3 = *(uint32_t*)&Wh_s[w * 16 + g + 8][k0 + 8];
            uint32_t al0 = *(uint32_t*)&Wl_s[w * 16 + g][k0];
            uint32_t al1 = *(uint32_t*)&Wl_s[w * 16 + g + 8][k0];
            uint32_t al2 = *(uint32_t*)&Wl_s[w * 16 + g][k0 + 8];
            uint32_t al3 = *(uint32_t*)&Wl_s[w * 16 + g + 8][k0 + 8];

#pragma unroll
            for (int jf = 0; jf < 8; jf++) {
                uint32_t bh0 = *(uint32_t*)&Xh_s[jf * 8 + g][k0];
                uint32_t bh1 = *(uint32_t*)&Xh_s[jf * 8 + g][k0 + 8];
                uint32_t bl0 = *(uint32_t*)&Xl_s[jf * 8 + g][k0];
                uint32_t bl1 = *(uint32_t*)&Xl_s[jf * 8 + g][k0 + 8];
                mma_bf16(acc[jf], ah0, ah1, ah2, ah3, bh0, bh1);
                mma_bf16(acc[jf], al0, al1, al2, al3, bh0, bh1);
                mma_bf16(acc[jf], ah0, ah1, ah2, ah3, bl0, bl1);
            }
        }
    }

    int m0 = mt * 128 + w * 16;
#pragma unroll
    for (int jf = 0; jf < 8; jf++) {
        int j = jt * 64 + jf * 8 + 2 * tig;
        *(float2*)&g_FVt[(size_t)(m0 + g) * B_ + j]     = make_float2(acc[jf][0], acc[jf][1]);
        *(float2*)&g_FVt[(size_t)(m0 + g + 8) * B_ + j] = make_float2(acc[jf][2], acc[jf][3]);
    }
}

// ---------------------------------------------------------------------------
// Kernel C (tensor forest): 256 threads, 128 b-rows x 8 n per block.
// resp staged as straight uint4 copies from g_respP (tf32, pair-interleaved).
// B-frags via single LDS.64 (pad 72 -> conflict-free per 16-lane phase).
// Grid (8 b-tiles of 128, 64 n-groups of 8) = 512 blocks.
// ---------------------------------------------------------------------------
__global__ void __launch_bounds__(256) k_forest(float* __restrict__ out) {
    __shared__ uint32_t resp_s[8][U_][72];   // tf32 bits, pair-interleaved, padded
    __shared__ float sc_s[48], of_s[48];

    int t    = threadIdx.x;
    int w    = t >> 5;
    int lane = t & 31;
    int g    = lane >> 2;
    int tig  = lane & 3;
    int bt   = blockIdx.x;   // 8 b-tiles of 128
    int ng   = blockIdx.y;   // 64 n-groups of 8

    if (t < 48) { sc_s[t] = g_sc[ng * 48 + t]; of_s[t] = g_of[ng * 48 + t]; }

    {   // stage 8 response tiles: 8192 words, pure uint4 copy
        const uint4* src = (const uint4*)(g_respP + (size_t)ng * 8 * (U_ * L_));
#pragma unroll
        for (int j = 0; j < 8; j++) {
            int idx = t + j * 256;            // uint4 index in [0,2048)
            uint4 v = src[idx];
            int fi = idx * 4;
            int row = fi >> 6, col = fi & 63;
            *(uint4*)&resp_s[row >> 4][row & 15][col] = v;
        }
    }
    __syncthreads();

    float acc[2][4] = {};
    int b_r0 = bt * 128 + w * 16 + g;    // rows b_r0, b_r0+8

    for (int nl = 0; nl < 8; nl++) {
        int n = ng * 8 + nl;
        const float* fvp = g_FVt + (size_t)n * 6 * B_;

        float h0[6], h1[6];
#pragma unroll
        for (int d = 0; d < 6; d++) {
            float sc = sc_s[nl * 6 + d], of = of_s[nl * 6 + d];
            float v0 = fvp[(size_t)d * B_ + b_r0]     * sc + of;
            float v1 = fvp[(size_t)d * B_ + b_r0 + 8] * sc + of;
            h0[d] = fminf(fmaxf(v0, 0.0f), 1.0f);
            h1[d] = fminf(fmaxf(v1, 0.0f), 1.0f);
        }

        float f0a = (tig & 1) ? (1.0f - h0[0]) : h0[0];
        float f0b = (tig & 1) ? (1.0f - h1[0]) : h1[0];
        float f1a = (tig & 2) ? (1.0f - h0[1]) : h0[1];
        float f1b = (tig & 2) ? (1.0f - h1[1]) : h1[1];
        float F0 = f0a * f1a, F1 = f0b * f1b;
        float A00 = F0 * h0[2], A01 = F0 * (1.0f - h0[2]);
        float A10 = F1 * h1[2], A11 = F1 * (1.0f - h1[2]);

        float S0[8], S1[8];
        {
            float p0 = h0[3], p1 = 1.0f - h0[3];
            float r0 = h0[4], r1 = 1.0f - h0[4];
            float q0 = p0 * r0, q1 = p1 * r0, q2 = p0 * r1, q3 = p1 * r1;
            float t5 = h0[5], u5 = 1.0f - h0[5];
            S0[0] = q0 * t5; S0[1] = q1 * t5; S0[2] = q2 * t5; S0[3] = q3 * t5;
            S0[4] = q0 * u5; S0[5] = q1 * u5; S0[6] = q2 * u5; S0[7] = q3 * u5;
        }
        {
            float p0 = h1[3], p1 = 1.0f - h1[3];
            float r0 = h1[4], r1 = 1.0f - h1[4];
            float q0 = p0 * r0, q1 = p1 * r0, q2 = p0 * r1, q3 = p1 * r1;
            float t5 = h1[5], u5 = 1.0f - h1[5];
            S1[0] = q0 * t5; S1[1] = q1 * t5; S1[2] = q2 * t5; S1[3] = q3 * t5;
            S1[4] = q0 * u5; S1[5] = q1 * u5; S1[6] = q2 * u5; S1[7] = q3 * u5;
        }

#pragma unroll
        for (int s = 0; s < 8; s++) {
            uint32_t a0 = __float_as_uint(A00 * S0[s]);
            uint32_t a1 = __float_as_uint(A10 * S1[s]);
            uint32_t a2 = __float_as_uint(A01 * S0[s]);
            uint32_t a3 = __float_as_uint(A11 * S1[s]);
#pragma unroll
            for (int nr = 0; nr < 2; nr++) {
                uint2 bb = *(const uint2*)&resp_s[nl][nr * 8 + g][8 * s + 2 * tig];
                mma_tf32(acc[nr], a0, a1, a2, a3, bb.x, bb.y);
            }
        }
    }

#pragma unroll
    for (int nr = 0; nr < 2; nr++) {
        int u = nr * 8 + 2 * tig;
        atomicAdd(&out[b_r0 * U_ + u],           acc[nr][0]);
        atomicAdd(&out[b_r0 * U_ + u + 1],       acc[nr][1]);
        atomicAdd(&out[(b_r0 + 8) * U_ + u],     acc[nr][2]);
        atomicAdd(&out[(b_r0 + 8) * U_ + u + 1], acc[nr][3]);
    }
}

// ---------------------------------------------------------------------------
extern "C" void kernel_launch(void* const* d_in, const int* in_sizes, int n_in,
                              void* d_out, int out_size) {
    const float* x    = (const float*)d_in[0];  // [B, I]
    const float* fsl  = (const float*)d_in[1];  // [I, N, D]
    const float* th   = (const float*)d_in[2];  // [N, D]
    const float* lt   = (const float*)d_in[3];  // [N, D]
    const float* resp = (const float*)d_in[4];  // [N, U, 2^D]
    float* out = (float*)d_out;                 // [B, U]

    cudaMemsetAsync(out, 0, (size_t)B_ * U_ * sizeof(float), 0);

    k_prep<<<512, 256>>>(fsl, x, th, lt, resp);
    k_wsplit<<<dim3(ND_ / 32, I_ / 32), 256>>>();
    k_gemm<<<dim3(B_ / 64, ND_ / 128), 256>>>();
    k_forest<<<dim3(B_ / 128, N_ / 8), 256>>>(out);
}